// round 3
// baseline (speedup 1.0000x reference)
#include <cuda_runtime.h>
#include <cuda_fp16.h>
#include <math.h>

#define NN 100000
#define NP 5000
#define NE 1000000
#define DA 20
#define RREP 8

// ---------------- scratch (device globals; no allocation) ----------------
__device__ __half g_nodesh[NN * 128];       // 25.6 MB fp16 nodes
__device__ float  g_query[NP * DA];
__device__ float  g_qproj[NP * 128];        // key_W @ query, pre-scaled by norm
__device__ float  g_cq[NP];                 // key_b . query * norm
__device__ int    g_cnt2[NP * RREP];
__device__ int    g_fillb[NP * RREP];
__device__ int    g_rowptr[NP + 1];
__device__ int    g_ssrc[NE];
__device__ float  g_agg[NP * 128];
__device__ float  g_attsum[NP];
__device__ float  g_M1[128 * 384];          // val_W @ W_ih^T  (K-major [k][n])
__device__ float  g_vb2[384];               // W_ih @ val_b
__device__ float  g_gi[NP * 384];
__device__ float  g_gh[NP * 384];

// ---------------- nodes fp32 -> fp16 ----------------
__global__ __launch_bounds__(256) void conv_kernel(const float4* __restrict__ nodes)
{
    int i = blockIdx.x * 256 + threadIdx.x;
    if (i >= NN * 128 / 4) return;
    float4 v = nodes[i];
    __half2 h0 = __floats2half2_rn(v.x, v.y);
    __half2 h1 = __floats2half2_rn(v.z, v.w);
    uint2 u;
    u.x = *reinterpret_cast<unsigned*>(&h0);
    u.y = *reinterpret_cast<unsigned*>(&h1);
    reinterpret_cast<uint2*>(g_nodesh)[i] = u;
}

// ---------------- query projection: g_query[M x 20] = [parts|grep] @ q_W + q_b
__global__ __launch_bounds__(128) void proj_query_kernel(
    const float* __restrict__ A0, const float* __restrict__ A1,
    const float* __restrict__ W, const float* __restrict__ bias)
{
    const int KDIM = 256;
    __shared__ alignas(16) float sW[KDIM * DA];
    __shared__ alignas(16) float sA[128 * 36];
    int tid = threadIdx.x;
    for (int i = tid; i < KDIM * DA; i += 128) sW[i] = W[i];

    float acc[DA];
#pragma unroll
    for (int c = 0; c < DA; c++) acc[c] = bias[c];

    int r0 = blockIdx.x * 128;
    int row = r0 + tid;

#pragma unroll 1
    for (int kc = 0; kc < KDIM; kc += 32) {
        const float* Asrc = (kc < 128) ? A0 : A1;
        int kbase = (kc < 128) ? kc : kc - 128;
        __syncthreads();
        int c = tid & 31, rb = tid >> 5;
#pragma unroll
        for (int i = 0; i < 32; i++) {
            int rr = rb + i * 4;
            int gr = r0 + rr;
            sA[rr * 36 + c] = (gr < NP) ? Asrc[gr * 128 + kbase + c] : 0.f;
        }
        __syncthreads();
        float a[32];
#pragma unroll
        for (int j = 0; j < 8; j++) {
            float4 v = *reinterpret_cast<const float4*>(&sA[tid * 36 + 4 * j]);
            a[4 * j + 0] = v.x; a[4 * j + 1] = v.y;
            a[4 * j + 2] = v.z; a[4 * j + 3] = v.w;
        }
#pragma unroll
        for (int kk = 0; kk < 32; kk++) {
            const float* wr = &sW[(kc + kk) * DA];
            float av = a[kk];
#pragma unroll
            for (int j = 0; j < 5; j++) {
                float4 w = *reinterpret_cast<const float4*>(wr + 4 * j);
                acc[4 * j + 0] = fmaf(av, w.x, acc[4 * j + 0]);
                acc[4 * j + 1] = fmaf(av, w.y, acc[4 * j + 1]);
                acc[4 * j + 2] = fmaf(av, w.z, acc[4 * j + 2]);
                acc[4 * j + 3] = fmaf(av, w.w, acc[4 * j + 3]);
            }
        }
    }
    if (row < NP) {
#pragma unroll
        for (int j = 0; j < 5; j++) {
            float4 v = make_float4(acc[4 * j], acc[4 * j + 1], acc[4 * j + 2], acc[4 * j + 3]);
            *reinterpret_cast<float4*>(&g_query[row * DA + 4 * j]) = v;
        }
    }
}

// ---------------- qproj[p][j] = norm * sum_c key_W[j][c] * query[p][c] ; cq = norm * key_b.query
__global__ __launch_bounds__(128) void qproj_kernel(
    const float* __restrict__ key_W, const float* __restrict__ key_b)
{
    __shared__ float sq[128 * DA];
    __shared__ float skb[DA];
    int tid = threadIdx.x;
    float w[DA];
#pragma unroll
    for (int c = 0; c < DA; c++) w[c] = key_W[tid * DA + c];
    if (tid < DA) skb[tid] = key_b[tid];

    int p0 = blockIdx.x * 128;
    int np = (p0 + 128 <= NP) ? 128 : (NP - p0);
    for (int i = tid; i < np * DA; i += 128) sq[i] = g_query[p0 * DA + i];
    __syncthreads();

    const float norm = 0.2236067977499789696f;
#pragma unroll 4
    for (int j = 0; j < np; j++) {
        float a = 0.f;
#pragma unroll
        for (int c = 0; c < DA; c++) a = fmaf(w[c], sq[j * DA + c], a);
        g_qproj[(p0 + j) * 128 + tid] = a * norm;
    }
    if (tid < np) {
        float cb = 0.f;
#pragma unroll
        for (int c = 0; c < DA; c++) cb = fmaf(skb[c], sq[tid * DA + c], cb);
        g_cq[p0 + tid] = cb * norm;
    }
}

// ---------------- CSR build (replicated counters) ----------------
__global__ void zero_cnt_kernel()
{
    int i = blockIdx.x * blockDim.x + threadIdx.x;
    if (i < NP * RREP) g_cnt2[i] = 0;
}

__global__ void count_kernel(const int* __restrict__ dst)
{
    int i = blockIdx.x * blockDim.x + threadIdx.x;
    if (i < NE) atomicAdd(&g_cnt2[dst[i] * RREP + (i & (RREP - 1))], 1);
}

__global__ __launch_bounds__(1024) void scan_kernel()
{
    __shared__ int ss[1024];
    const int TOT = NP * RREP;     // 40000
    const int BP = 40;
    int tid = threadIdx.x;
    int base = tid * BP;
    int s = 0;
    for (int i = 0; i < BP; i++) {
        int b = base + i;
        if (b < TOT) s += g_cnt2[b];
    }
    ss[tid] = s;
    __syncthreads();
    for (int off = 1; off < 1024; off <<= 1) {
        int add = (tid >= off) ? ss[tid - off] : 0;
        __syncthreads();
        ss[tid] += add;
        __syncthreads();
    }
    int run = ss[tid] - s;  // exclusive prefix of this thread's chunk
    for (int i = 0; i < BP; i++) {
        int b = base + i;
        if (b < TOT) {
            int c = g_cnt2[b];
            g_fillb[b] = run;
            if ((b & (RREP - 1)) == 0) g_rowptr[b / RREP] = run;
            run += c;
        }
    }
    if (tid == 1023) g_rowptr[NP] = ss[1023];
}

__global__ void scatter_kernel(const int* __restrict__ src, const int* __restrict__ dst)
{
    int i = blockIdx.x * blockDim.x + threadIdx.x;
    if (i >= NE) return;
    int d = dst[i];
    int pos = atomicAdd(&g_fillb[d * RREP + (i & (RREP - 1))], 1);
    g_ssrc[pos] = src[i];
}

// ---------------- fused att + aggregation: warp per particle ----------------
__device__ __forceinline__ void unpk(uint2 u, float* o)
{
    __half2 h0 = *reinterpret_cast<__half2*>(&u.x);
    __half2 h1 = *reinterpret_cast<__half2*>(&u.y);
    float2 f0 = __half22float2(h0), f1 = __half22float2(h1);
    o[0] = f0.x; o[1] = f0.y; o[2] = f1.x; o[3] = f1.y;
}

__global__ __launch_bounds__(128) void aggregate_kernel()
{
    int p = blockIdx.x * 4 + (threadIdx.x >> 5);
    if (p >= NP) return;
    int lane = threadIdx.x & 31;
    int sub = lane & 7;     // 16-col slice within group
    int grp = lane >> 3;    // edge slot (0..3)

    float qv[16];
#pragma unroll
    for (int j = 0; j < 4; j++) {
        float4 v = *reinterpret_cast<const float4*>(&g_qproj[p * 128 + sub * 16 + 4 * j]);
        qv[4 * j + 0] = v.x; qv[4 * j + 1] = v.y;
        qv[4 * j + 2] = v.z; qv[4 * j + 3] = v.w;
    }
    float cb = g_cq[p];

    int beg = g_rowptr[p], end = g_rowptr[p + 1];
    float acc[16];
#pragma unroll
    for (int k = 0; k < 16; k++) acc[k] = 0.f;
    float asum = 0.f;

    for (int i = beg; i < end; i += 4) {
        int e = i + grp;
        bool valid = (e < end);
        int s = g_ssrc[valid ? e : beg];
        const uint2* rp = reinterpret_cast<const uint2*>(g_nodesh + (size_t)s * 128) + sub * 4;
        uint2 u0 = __ldg(rp + 0), u1 = __ldg(rp + 1), u2 = __ldg(rp + 2), u3 = __ldg(rp + 3);
        float v[16];
        unpk(u0, v + 0); unpk(u1, v + 4); unpk(u2, v + 8); unpk(u3, v + 12);
        float d = 0.f;
#pragma unroll
        for (int k = 0; k < 16; k++) d = fmaf(v[k], qv[k], d);
        d += __shfl_xor_sync(0xffffffffu, d, 1);
        d += __shfl_xor_sync(0xffffffffu, d, 2);
        d += __shfl_xor_sync(0xffffffffu, d, 4);
        float att = valid ? (d + cb) : 0.f;
        if (sub == 0) asum += att;
#pragma unroll
        for (int k = 0; k < 16; k++) acc[k] = fmaf(att, v[k], acc[k]);
    }

#pragma unroll
    for (int k = 0; k < 16; k++) {
        acc[k] += __shfl_xor_sync(0xffffffffu, acc[k], 8);
        acc[k] += __shfl_xor_sync(0xffffffffu, acc[k], 16);
    }
    asum += __shfl_xor_sync(0xffffffffu, asum, 8);
    asum += __shfl_xor_sync(0xffffffffu, asum, 16);

    if (grp == 0) {
        float4* op = reinterpret_cast<float4*>(g_agg + p * 128 + sub * 16);
        op[0] = make_float4(acc[0], acc[1], acc[2], acc[3]);
        op[1] = make_float4(acc[4], acc[5], acc[6], acc[7]);
        op[2] = make_float4(acc[8], acc[9], acc[10], acc[11]);
        op[3] = make_float4(acc[12], acc[13], acc[14], acc[15]);
    }
    if (lane == 0) g_attsum[p] = asum;
}

// ---------------- vb2[n] = sum_p W_ih[n][p] * val_b[p] ----------------
__global__ __launch_bounds__(384) void vb2_kernel(
    const float* __restrict__ W_ih, const float* __restrict__ val_b)
{
    __shared__ float sv[128];
    int tid = threadIdx.x;
    if (tid < 128) sv[tid] = val_b[tid];
    __syncthreads();
    float a = 0.f;
#pragma unroll 8
    for (int k = 0; k < 128; k++) a = fmaf(W_ih[tid * 128 + k], sv[k], a);
    g_vb2[tid] = a;
}

// ---------------- SGEMM (K=128, N=384, 128x128 tiles) ----------------
// MODE 0: M1 = val_W @ W_ih^T            (A=val_W [128x128], B=W_ih N-major, no bias)
// MODE 1: gh = parts @ W_hh^T + b_hh     (A=parts,          B=W_hh N-major)
// MODE 2: gi = agg @ M1 + attsum*vb2 + b_ih  (A=g_agg, B=g_M1 K-major)
template <int MODE>
__global__ __launch_bounds__(256) void sgemm_kernel(
    const float* __restrict__ Aparam, const float* __restrict__ Bparam,
    const float* __restrict__ bias, int M)
{
    const int K = 128;
    const int NTOT = 384;
    const bool B_NK = (MODE != 2);
    const float* __restrict__ A = (MODE == 2) ? g_agg : Aparam;
    const float* __restrict__ B = (MODE == 2) ? g_M1 : Bparam;
    float* __restrict__ C = (MODE == 0) ? g_M1 : (MODE == 1) ? g_gh : g_gi;

    __shared__ alignas(16) float sA[32 * 132];
    __shared__ alignas(16) float sB[32 * 132];
    int tid = threadIdx.x;
    int m0 = blockIdx.x * 128;
    int n0 = blockIdx.y * 128;
    int tx = tid & 15, ty = tid >> 4;

    float acc[8][8];
#pragma unroll
    for (int i = 0; i < 8; i++)
#pragma unroll
        for (int j = 0; j < 8; j++) acc[i][j] = 0.f;

#pragma unroll 1
    for (int kc = 0; kc < K; kc += 32) {
        __syncthreads();
        {   // stage A transposed: sA[k][m]
            int col4 = (tid & 7) * 4;
            int rowb = tid >> 3;
#pragma unroll
            for (int pp = 0; pp < 4; pp++) {
                int r = rowb + pp * 32;
                float4 v = make_float4(0.f, 0.f, 0.f, 0.f);
                if (m0 + r < M)
                    v = *reinterpret_cast<const float4*>(&A[(m0 + r) * K + kc + col4]);
                sA[(col4 + 0) * 132 + r] = v.x;
                sA[(col4 + 1) * 132 + r] = v.y;
                sA[(col4 + 2) * 132 + r] = v.z;
                sA[(col4 + 3) * 132 + r] = v.w;
            }
        }
        if (!B_NK) {   // B [K x NTOT]
            int n4 = (tid & 31) * 4;
            int kr = tid >> 5;
#pragma unroll
            for (int pp = 0; pp < 4; pp++) {
                int k = kr + pp * 8;
                float4 v = *reinterpret_cast<const float4*>(&B[(kc + k) * NTOT + n0 + n4]);
                *reinterpret_cast<float4*>(&sB[k * 132 + n4]) = v;
            }
        } else {       // B [N x K]
            int k4 = (tid & 7) * 4;
            int nr = tid >> 3;
#pragma unroll
            for (int pp = 0; pp < 4; pp++) {
                int n = nr + pp * 32;
                float4 v = *reinterpret_cast<const float4*>(&B[(n0 + n) * K + kc + k4]);
                sB[(k4 + 0) * 132 + n] = v.x;
                sB[(k4 + 1) * 132 + n] = v.y;
                sB[(k4 + 2) * 132 + n] = v.z;
                sB[(k4 + 3) * 132 + n] = v.w;
            }
        }
        __syncthreads();
#pragma unroll 8
        for (int k = 0; k < 32; k++) {
            float4 a0 = *reinterpret_cast<const float4*>(&sA[k * 132 + ty * 8]);
            float4 a1 = *reinterpret_cast<const float4*>(&sA[k * 132 + ty * 8 + 4]);
            float4 b0 = *reinterpret_cast<const float4*>(&sB[k * 132 + tx * 8]);
            float4 b1 = *reinterpret_cast<const float4*>(&sB[k * 132 + tx * 8 + 4]);
            float av[8] = {a0.x, a0.y, a0.z, a0.w, a1.x, a1.y, a1.z, a1.w};
            float bv[8] = {b0.x, b0.y, b0.z, b0.w, b1.x, b1.y, b1.z, b1.w};
#pragma unroll
            for (int i = 0; i < 8; i++)
#pragma unroll
                for (int j = 0; j < 8; j++)
                    acc[i][j] = fmaf(av[i], bv[j], acc[i][j]);
        }
    }

#pragma unroll
    for (int i = 0; i < 8; i++) {
        int m = m0 + ty * 8 + i;
        if (m < M) {
            float rs = (MODE == 2) ? g_attsum[m] : 0.f;
#pragma unroll
            for (int j = 0; j < 8; j++) {
                int n = n0 + tx * 8 + j;
                float v = acc[i][j];
                if (MODE != 0) v += bias[n];
                if (MODE == 2) v += rs * g_vb2[n];
                C[m * NTOT + n] = v;
            }
        }
    }
}

// ---------------- fused GRU gates + LayerNorm + MLP + residual ----------------
__global__ __launch_bounds__(128) void gru_kernel(
    const float* __restrict__ ph,
    const float* __restrict__ lng, const float* __restrict__ lnb,
    const float* __restrict__ W1, const float* __restrict__ b1,
    const float* __restrict__ W2, const float* __restrict__ b2,
    float* __restrict__ out)
{
    __shared__ alignas(16) float sW1[128 * 64];
    __shared__ float sLN[128];
    __shared__ float sHID[64];
    __shared__ float sred[8];
    int tid = threadIdx.x;
    int lane = tid & 31, wid = tid >> 5;
    for (int i = tid; i < 128 * 64; i += 128) sW1[i] = W1[i];
    float gln = lng[tid], bln = lnb[tid], bb2 = b2[tid];

    int p0 = blockIdx.x * 16;
    int pend = (p0 + 16 < NP) ? p0 + 16 : NP;
    for (int p = p0; p < pend; p++) {
        __syncthreads();
        float h = ph[p * 128 + tid];
        const float* gip = g_gi + p * 384;
        const float* ghp = g_gh + p * 384;
        float ir = gip[tid], iz = gip[128 + tid], in_ = gip[256 + tid];
        float hr = ghp[tid], hz = ghp[128 + tid], hn = ghp[256 + tid];
        float r = 1.f / (1.f + expf(-(ir + hr)));
        float z = 1.f / (1.f + expf(-(iz + hz)));
        float n = tanhf(in_ + r * hn);
        float x = (1.f - z) * n + z * h;

        float s1 = x, s2 = x * x;
#pragma unroll
        for (int o = 16; o > 0; o >>= 1) {
            s1 += __shfl_down_sync(0xffffffffu, s1, o);
            s2 += __shfl_down_sync(0xffffffffu, s2, o);
        }
        if (lane == 0) { sred[wid] = s1; sred[4 + wid] = s2; }
        __syncthreads();
        float S1 = sred[0] + sred[1] + sred[2] + sred[3];
        float S2 = sred[4] + sred[5] + sred[6] + sred[7];
        float mu = S1 * (1.f / 128.f);
        float var = S2 * (1.f / 128.f) - mu * mu;
        float ln = (x - mu) * (1.f / sqrtf(var + 1e-5f)) * gln + bln;
        sLN[tid] = ln;
        __syncthreads();
        if (tid < 64) {
            float a = b1[tid];
#pragma unroll 8
            for (int k = 0; k < 128; k++) a = fmaf(sLN[k], sW1[k * 64 + tid], a);
            sHID[tid] = fmaxf(a, 0.f);
        }
        __syncthreads();
        float o = bb2;
#pragma unroll 8
        for (int j = 0; j < 64; j++) o = fmaf(sHID[j], W2[j * 128 + tid], o);
        out[p * 128 + tid] = h + o;
    }
}

// ---------------- launch ----------------
extern "C" void kernel_launch(void* const* d_in, const int* in_sizes, int n_in,
                              void* d_out, int out_size)
{
    const float* nodes = (const float*)d_in[0];
    const float* parts = (const float*)d_in[1];
    const float* grep  = (const float*)d_in[2];
    const int*   src   = (const int*)d_in[3];
    const int*   dst   = (const int*)d_in[4];
    const float* key_W = (const float*)d_in[5];
    const float* key_b = (const float*)d_in[6];
    const float* val_W = (const float*)d_in[7];
    const float* val_b = (const float*)d_in[8];
    const float* q_W   = (const float*)d_in[9];
    const float* q_b   = (const float*)d_in[10];
    const float* W_ih  = (const float*)d_in[11];
    const float* W_hh  = (const float*)d_in[12];
    const float* b_ih  = (const float*)d_in[13];
    const float* b_hh  = (const float*)d_in[14];
    const float* ln_g  = (const float*)d_in[15];
    const float* ln_b  = (const float*)d_in[16];
    const float* W1    = (const float*)d_in[17];
    const float* b1    = (const float*)d_in[18];
    const float* W2    = (const float*)d_in[19];
    const float* b2    = (const float*)d_in[20];
    float* out = (float*)d_out;

    conv_kernel<<<12500, 256>>>((const float4*)nodes);
    proj_query_kernel<<<(NP + 127) / 128, 128>>>(parts, grep, q_W, q_b);
    qproj_kernel<<<(NP + 127) / 128, 128>>>(key_W, key_b);
    zero_cnt_kernel<<<(NP * RREP + 255) / 256, 256>>>();
    count_kernel<<<(NE + 255) / 256, 256>>>(dst);
    scan_kernel<<<1, 1024>>>();
    scatter_kernel<<<(NE + 255) / 256, 256>>>(src, dst);

    // constant folds + gh (independent of the aggregation chain)
    sgemm_kernel<0><<<dim3(1, 3), 256>>>(val_W, W_ih, nullptr, 128);
    vb2_kernel<<<1, 384>>>(W_ih, val_b);
    sgemm_kernel<1><<<dim3((NP + 127) / 128, 3), 256>>>(parts, W_hh, b_hh, NP);

    aggregate_kernel<<<(NP + 3) / 4, 128>>>();
    sgemm_kernel<2><<<dim3((NP + 127) / 128, 3), 256>>>(nullptr, nullptr, b_ih, NP);

    gru_kernel<<<(NP + 15) / 16, 128>>>(parts, ln_g, ln_b, W1, b1, W2, b2, out);
}

// round 6
// speedup vs baseline: 1.0514x; 1.0514x over previous
#include <cuda_runtime.h>
#include <cuda_fp16.h>
#include <math.h>

#define NN 100000
#define NP 5000
#define NE 1000000
#define DA 20
#define RREP 8

// ---------------- scratch (device globals; no allocation) ----------------
__device__ __half g_nodesh[NN * 128];       // 25.6 MB fp16 nodes
__device__ float  g_qproj[NP * 128];        // key_W @ query, pre-scaled by norm
__device__ float  g_cq[NP];                 // key_b . query * norm
__device__ int    g_cnt2[NP * RREP];
__device__ int    g_fillb[NP * RREP];
__device__ int    g_rowptr[NP + 1];
__device__ int    g_ssrc[NE];
__device__ float  g_agg[NP * 128];
__device__ float  g_attsum[NP];
__device__ float  g_M1[128 * 384];          // val_W @ W_ih^T  (K-major [k][n])
__device__ float  g_vb2[384];               // W_ih @ val_b
__device__ float  g_gi[NP * 384];
__device__ float  g_gh[NP * 384];

// ---------------- nodes fp32 -> fp16 (+ zero counters, fused) ----------------
__global__ __launch_bounds__(256) void conv_kernel(const float4* __restrict__ nodes)
{
    int i = blockIdx.x * 256 + threadIdx.x;
    if (i < NP * RREP) g_cnt2[i] = 0;
    if (i >= NN * 128 / 4) return;
    float4 v = nodes[i];
    __half2 h0 = __floats2half2_rn(v.x, v.y);
    __half2 h1 = __floats2half2_rn(v.z, v.w);
    uint2 u;
    u.x = *reinterpret_cast<unsigned*>(&h0);
    u.y = *reinterpret_cast<unsigned*>(&h1);
    reinterpret_cast<uint2*>(g_nodesh)[i] = u;
}

// ------- fused: query = [parts|grep] @ q_W + q_b ; qproj = key_W @ query^T * norm ; cq
__global__ __launch_bounds__(128) void query_kernel(
    const float* __restrict__ A0, const float* __restrict__ A1,
    const float* __restrict__ W, const float* __restrict__ bias,
    const float* __restrict__ key_W, const float* __restrict__ key_b)
{
    const int KDIM = 256;
    __shared__ alignas(16) float sW[KDIM * DA];     // 20 KB
    __shared__ alignas(16) float sA[128 * 36];      // 18.4 KB (reused as sq)
    int tid = threadIdx.x;
    for (int i = tid; i < KDIM * DA; i += 128) sW[i] = W[i];

    float acc[DA];
#pragma unroll
    for (int c = 0; c < DA; c++) acc[c] = bias[c];

    int r0 = blockIdx.x * 128;
    int row = r0 + tid;
    int np = (r0 + 128 <= NP) ? 128 : (NP - r0);

#pragma unroll 1
    for (int kc = 0; kc < KDIM; kc += 32) {
        const float* Asrc = (kc < 128) ? A0 : A1;
        int kbase = (kc < 128) ? kc : kc - 128;
        __syncthreads();
        int c = tid & 31, rb = tid >> 5;
#pragma unroll
        for (int i = 0; i < 32; i++) {
            int rr = rb + i * 4;
            int gr = r0 + rr;
            sA[rr * 36 + c] = (gr < NP) ? Asrc[gr * 128 + kbase + c] : 0.f;
        }
        __syncthreads();
        float a[32];
#pragma unroll
        for (int j = 0; j < 8; j++) {
            float4 v = *reinterpret_cast<const float4*>(&sA[tid * 36 + 4 * j]);
            a[4 * j + 0] = v.x; a[4 * j + 1] = v.y;
            a[4 * j + 2] = v.z; a[4 * j + 3] = v.w;
        }
#pragma unroll
        for (int kk = 0; kk < 32; kk++) {
            const float* wr = &sW[(kc + kk) * DA];
            float av = a[kk];
#pragma unroll
            for (int j = 0; j < 5; j++) {
                float4 w = *reinterpret_cast<const float4*>(wr + 4 * j);
                acc[4 * j + 0] = fmaf(av, w.x, acc[4 * j + 0]);
                acc[4 * j + 1] = fmaf(av, w.y, acc[4 * j + 1]);
                acc[4 * j + 2] = fmaf(av, w.z, acc[4 * j + 2]);
                acc[4 * j + 3] = fmaf(av, w.w, acc[4 * j + 3]);
            }
        }
    }

    const float norm = 0.2236067977499789696f;
    __syncthreads();
    // stage query rows into sA (reused as sq[128][20]); compute cq
    float* sq = sA;
    if (row < NP) {
        float cb = 0.f;
#pragma unroll
        for (int c = 0; c < DA; c++) {
            sq[tid * DA + c] = acc[c];
            cb = fmaf(key_b[c], acc[c], cb);
        }
        g_cq[row] = cb * norm;
    } else {
#pragma unroll
        for (int c = 0; c < DA; c++) sq[tid * DA + c] = 0.f;
    }
    __syncthreads();

    // qproj: thread tid = output column
    float w[DA];
#pragma unroll
    for (int c = 0; c < DA; c++) w[c] = key_W[tid * DA + c];
#pragma unroll 4
    for (int j = 0; j < np; j++) {
        float a = 0.f;
#pragma unroll
        for (int c = 0; c < DA; c++) a = fmaf(w[c], sq[j * DA + c], a);
        g_qproj[(r0 + j) * 128 + tid] = a * norm;
    }
}

// ---------------- CSR build (replicated counters) ----------------
__global__ void count_kernel(const int* __restrict__ dst)
{
    int i = blockIdx.x * blockDim.x + threadIdx.x;
    if (i < NE) atomicAdd(&g_cnt2[dst[i] * RREP + (i & (RREP - 1))], 1);
}

__global__ __launch_bounds__(1024) void scan_kernel()
{
    __shared__ int ss[1024];
    const int TOT = NP * RREP;     // 40000
    const int BP = 40;
    int tid = threadIdx.x;
    int base = tid * BP;
    int s = 0;
#pragma unroll
    for (int i = 0; i < BP; i++) {
        int b = base + i;
        if (b < TOT) s += g_cnt2[b];
    }
    ss[tid] = s;
    __syncthreads();
    for (int off = 1; off < 1024; off <<= 1) {
        int add = (tid >= off) ? ss[tid - off] : 0;
        __syncthreads();
        ss[tid] += add;
        __syncthreads();
    }
    int run = ss[tid] - s;  // exclusive prefix of this thread's chunk
#pragma unroll
    for (int i = 0; i < BP; i++) {
        int b = base + i;
        if (b < TOT) {
            int c = g_cnt2[b];
            g_fillb[b] = run;
            if ((b & (RREP - 1)) == 0) g_rowptr[b / RREP] = run;
            run += c;
        }
    }
    if (tid == 1023) g_rowptr[NP] = ss[1023];
}

__global__ void scatter_kernel(const int* __restrict__ src, const int* __restrict__ dst)
{
    int i = blockIdx.x * blockDim.x + threadIdx.x;
    if (i >= NE) return;
    int d = dst[i];
    int pos = atomicAdd(&g_fillb[d * RREP + (i & (RREP - 1))], 1);
    g_ssrc[pos] = src[i];
}

// ---------------- fused att + aggregation: warp per particle ----------------
// Lane layout: grp = lane>>3 (edge slot 0..3), sub = lane&7.
// Lane handles columns [sub*8, sub*8+8) and [64+sub*8, 64+sub*8+8):
// each uint4 (16B = 8 halves) load is CONTIGUOUS across the 8-lane group
// -> full 128B sector utilization per LDG.128 wavefront.
__device__ __forceinline__ void unpk8(uint4 u, float* o)
{
    __half2 h;
    h = *reinterpret_cast<__half2*>(&u.x); { float2 f = __half22float2(h); o[0] = f.x; o[1] = f.y; }
    h = *reinterpret_cast<__half2*>(&u.y); { float2 f = __half22float2(h); o[2] = f.x; o[3] = f.y; }
    h = *reinterpret_cast<__half2*>(&u.z); { float2 f = __half22float2(h); o[4] = f.x; o[5] = f.y; }
    h = *reinterpret_cast<__half2*>(&u.w); { float2 f = __half22float2(h); o[6] = f.x; o[7] = f.y; }
}

__global__ __launch_bounds__(128) void aggregate_kernel()
{
    int p = blockIdx.x * 4 + (threadIdx.x >> 5);
    if (p >= NP) return;
    int lane = threadIdx.x & 31;
    int sub = lane & 7;
    int grp = lane >> 3;

    float qv[16];
#pragma unroll
    for (int j = 0; j < 2; j++) {
        float4 v = *reinterpret_cast<const float4*>(&g_qproj[p * 128 + sub * 8 + 4 * j]);
        qv[4 * j + 0] = v.x; qv[4 * j + 1] = v.y;
        qv[4 * j + 2] = v.z; qv[4 * j + 3] = v.w;
    }
#pragma unroll
    for (int j = 0; j < 2; j++) {
        float4 v = *reinterpret_cast<const float4*>(&g_qproj[p * 128 + 64 + sub * 8 + 4 * j]);
        qv[8 + 4 * j + 0] = v.x; qv[8 + 4 * j + 1] = v.y;
        qv[8 + 4 * j + 2] = v.z; qv[8 + 4 * j + 3] = v.w;
    }
    float cb = g_cq[p];

    int beg = g_rowptr[p], end = g_rowptr[p + 1];
    float acc[16];
#pragma unroll
    for (int k = 0; k < 16; k++) acc[k] = 0.f;
    float asum = 0.f;

    for (int i = beg; i < end; i += 4) {
        int e = i + grp;
        bool valid = (e < end);
        int s = g_ssrc[valid ? e : beg];
        const uint4* rowp = reinterpret_cast<const uint4*>(g_nodesh + (size_t)s * 128);
        uint4 u0 = __ldg(rowp + sub);        // bytes [sub*16, +16)   -> cols sub*8..+8
        uint4 u1 = __ldg(rowp + 8 + sub);    // bytes [128+sub*16,..) -> cols 64+sub*8..+8
        float v[16];
        unpk8(u0, v);
        unpk8(u1, v + 8);
        float d = 0.f;
#pragma unroll
        for (int k = 0; k < 16; k++) d = fmaf(v[k], qv[k], d);
        d += __shfl_xor_sync(0xffffffffu, d, 1);
        d += __shfl_xor_sync(0xffffffffu, d, 2);
        d += __shfl_xor_sync(0xffffffffu, d, 4);
        float att = valid ? (d + cb) : 0.f;
        if (sub == 0) asum += att;
#pragma unroll
        for (int k = 0; k < 16; k++) acc[k] = fmaf(att, v[k], acc[k]);
    }

#pragma unroll
    for (int k = 0; k < 16; k++) {
        acc[k] += __shfl_xor_sync(0xffffffffu, acc[k], 8);
        acc[k] += __shfl_xor_sync(0xffffffffu, acc[k], 16);
    }
    asum += __shfl_xor_sync(0xffffffffu, asum, 8);
    asum += __shfl_xor_sync(0xffffffffu, asum, 16);

    if (grp == 0) {
        float4* op0 = reinterpret_cast<float4*>(g_agg + p * 128 + sub * 8);
        op0[0] = make_float4(acc[0], acc[1], acc[2], acc[3]);
        op0[1] = make_float4(acc[4], acc[5], acc[6], acc[7]);
        float4* op1 = reinterpret_cast<float4*>(g_agg + p * 128 + 64 + sub * 8);
        op1[0] = make_float4(acc[8], acc[9], acc[10], acc[11]);
        op1[1] = make_float4(acc[12], acc[13], acc[14], acc[15]);
    }
    if (lane == 0) g_attsum[p] = asum;
}

// ---------------- vb2[n] = sum_p W_ih[n][p] * val_b[p] ----------------
__global__ __launch_bounds__(384) void vb2_kernel(
    const float* __restrict__ W_ih, const float* __restrict__ val_b)
{
    __shared__ float sv[128];
    int tid = threadIdx.x;
    if (tid < 128) sv[tid] = val_b[tid];
    __syncthreads();
    float a = 0.f;
#pragma unroll 8
    for (int k = 0; k < 128; k++) a = fmaf(W_ih[tid * 128 + k], sv[k], a);
    g_vb2[tid] = a;
}

// ---------------- SGEMM (K=128, N=384, 128x128 tiles) ----------------
// MODE 0: M1 = val_W @ W_ih^T                (A=val_W, B=W_ih N-major)
// MODE 1: gh = parts @ W_hh^T + b_hh         (A=parts, B=W_hh N-major)
// MODE 2: gi = agg @ M1 + attsum*vb2 + b_ih  (A=g_agg, B=g_M1 K-major)
template <int MODE>
__global__ __launch_bounds__(256) void sgemm_kernel(
    const float* __restrict__ Aparam, const float* __restrict__ Bparam,
    const float* __restrict__ bias, int M)
{
    const int K = 128;
    const int NTOT = 384;
    const bool B_NK = (MODE != 2);
    const float* __restrict__ A = (MODE == 2) ? g_agg : Aparam;
    const float* __restrict__ B = (MODE == 2) ? g_M1 : Bparam;
    float* __restrict__ C = (MODE == 0) ? g_M1 : (MODE == 1) ? g_gh : g_gi;

    __shared__ alignas(16) float sA[32 * 132];
    __shared__ alignas(16) float sB[32 * 132];
    int tid = threadIdx.x;
    int m0 = blockIdx.x * 128;
    int n0 = blockIdx.y * 128;
    int tx = tid & 15, ty = tid >> 4;

    float acc[8][8];
#pragma unroll
    for (int i = 0; i < 8; i++)
#pragma unroll
        for (int j = 0; j < 8; j++) acc[i][j] = 0.f;

#pragma unroll 1
    for (int kc = 0; kc < K; kc += 32) {
        __syncthreads();
        {   // stage A transposed: sA[k][m]
            int col4 = (tid & 7) * 4;
            int rowb = tid >> 3;
#pragma unroll
            for (int pp = 0; pp < 4; pp++) {
                int r = rowb + pp * 32;
                float4 v = make_float4(0.f, 0.f, 0.f, 0.f);
                if (m0 + r < M)
                    v = *reinterpret_cast<const float4*>(&A[(m0 + r) * K + kc + col4]);
                sA[(col4 + 0) * 132 + r] = v.x;
                sA[(col4 + 1) * 132 + r] = v.y;
                sA[(col4 + 2) * 132 + r] = v.z;
                sA[(col4 + 3) * 132 + r] = v.w;
            }
        }
        if (!B_NK) {   // B [K x NTOT]
            int n4 = (tid & 31) * 4;
            int kr = tid >> 5;
#pragma unroll
            for (int pp = 0; pp < 4; pp++) {
                int k = kr + pp * 8;
                float4 v = *reinterpret_cast<const float4*>(&B[(kc + k) * NTOT + n0 + n4]);
                *reinterpret_cast<float4*>(&sB[k * 132 + n4]) = v;
            }
        } else {       // B [N x K]
            int k4 = (tid & 7) * 4;
            int nr = tid >> 3;
#pragma unroll
            for (int pp = 0; pp < 4; pp++) {
                int n = nr + pp * 32;
                float4 v = *reinterpret_cast<const float4*>(&B[(n0 + n) * K + kc + k4]);
                sB[(k4 + 0) * 132 + n] = v.x;
                sB[(k4 + 1) * 132 + n] = v.y;
                sB[(k4 + 2) * 132 + n] = v.z;
                sB[(k4 + 3) * 132 + n] = v.w;
            }
        }
        __syncthreads();
#pragma unroll 8
        for (int k = 0; k < 32; k++) {
            float4 a0 = *reinterpret_cast<const float4*>(&sA[k * 132 + ty * 8]);
            float4 a1 = *reinterpret_cast<const float4*>(&sA[k * 132 + ty * 8 + 4]);
            float4 b0 = *reinterpret_cast<const float4*>(&sB[k * 132 + tx * 8]);
            float4 b1 = *reinterpret_cast<const float4*>(&sB[k * 132 + tx * 8 + 4]);
            float av[8] = {a0.x, a0.y, a0.z, a0.w, a1.x, a1.y, a1.z, a1.w};
            float bv[8] = {b0.x, b0.y, b0.z, b0.w, b1.x, b1.y, b1.z, b1.w};
#pragma unroll
            for (int i = 0; i < 8; i++)
#pragma unroll
                for (int j = 0; j < 8; j++)
                    acc[i][j] = fmaf(av[i], bv[j], acc[i][j]);
        }
    }

#pragma unroll
    for (int i = 0; i < 8; i++) {
        int m = m0 + ty * 8 + i;
        if (m < M) {
            float rs = (MODE == 2) ? g_attsum[m] : 0.f;
#pragma unroll
            for (int j = 0; j < 8; j++) {
                int n = n0 + tx * 8 + j;
                float v = acc[i][j];
                if (MODE != 0) v += bias[n];
                if (MODE == 2) v += rs * g_vb2[n];
                C[m * NTOT + n] = v;
            }
        }
    }
}

// ---------------- fused GRU gates + LayerNorm + MLP + residual ----------------
__global__ __launch_bounds__(128) void gru_kernel(
    const float* __restrict__ ph,
    const float* __restrict__ lng, const float* __restrict__ lnb,
    const float* __restrict__ W1, const float* __restrict__ b1,
    const float* __restrict__ W2, const float* __restrict__ b2,
    float* __restrict__ out)
{
    __shared__ alignas(16) float sW1[128 * 64];
    __shared__ float sLN[128];
    __shared__ float sHID[64];
    __shared__ float sred[8];
    int tid = threadIdx.x;
    int lane = tid & 31, wid = tid >> 5;
    for (int i = tid; i < 128 * 64; i += 128) sW1[i] = W1[i];
    float gln = lng[tid], bln = lnb[tid], bb2 = b2[tid];

    int p0 = blockIdx.x * 16;
    int pend = (p0 + 16 < NP) ? p0 + 16 : NP;
    for (int p = p0; p < pend; p++) {
        __syncthreads();
        float h = ph[p * 128 + tid];
        const float* gip = g_gi + p * 384;
        const float* ghp = g_gh + p * 384;
        float ir = gip[tid], iz = gip[128 + tid], in_ = gip[256 + tid];
        float hr = ghp[tid], hz = ghp[128 + tid], hn = ghp[256 + tid];
        float r = 1.f / (1.f + expf(-(ir + hr)));
        float z = 1.f / (1.f + expf(-(iz + hz)));
        float n = tanhf(in_ + r * hn);
        float x = (1.f - z) * n + z * h;

        float s1 = x, s2 = x * x;
#pragma unroll
        for (int o = 16; o > 0; o >>= 1) {
            s1 += __shfl_down_sync(0xffffffffu, s1, o);
            s2 += __shfl_down_sync(0xffffffffu, s2, o);
        }
        if (lane == 0) { sred[wid] = s1; sred[4 + wid] = s2; }
        __syncthreads();
        float S1 = sred[0] + sred[1] + sred[2] + sred[3];
        float S2 = sred[4] + sred[5] + sred[6] + sred[7];
        float mu = S1 * (1.f / 128.f);
        float var = S2 * (1.f / 128.f) - mu * mu;
        float ln = (x - mu) * (1.f / sqrtf(var + 1e-5f)) * gln + bln;
        sLN[tid] = ln;
        __syncthreads();
        if (tid < 64) {
            float a = b1[tid];
#pragma unroll 8
            for (int k = 0; k < 128; k++) a = fmaf(sLN[k], sW1[k * 64 + tid], a);
            sHID[tid] = fmaxf(a, 0.f);
        }
        __syncthreads();
        float o = bb2;
#pragma unroll 8
        for (int j = 0; j < 64; j++) o = fmaf(sHID[j], W2[j * 128 + tid], o);
        out[p * 128 + tid] = h + o;
    }
}

// ---------------- launch ----------------
extern "C" void kernel_launch(void* const* d_in, const int* in_sizes, int n_in,
                              void* d_out, int out_size)
{
    const float* nodes = (const float*)d_in[0];
    const float* parts = (const float*)d_in[1];
    const float* grep  = (const float*)d_in[2];
    const int*   src   = (const int*)d_in[3];
    const int*   dst   = (const int*)d_in[4];
    const float* key_W = (const float*)d_in[5];
    const float* key_b = (const float*)d_in[6];
    const float* val_W = (const float*)d_in[7];
    const float* val_b = (const float*)d_in[8];
    const float* q_W   = (const float*)d_in[9];
    const float* q_b   = (const float*)d_in[10];
    const float* W_ih  = (const float*)d_in[11];
    const float* W_hh  = (const float*)d_in[12];
    const float* b_ih  = (const float*)d_in[13];
    const float* b_hh  = (const float*)d_in[14];
    const float* ln_g  = (const float*)d_in[15];
    const float* ln_b  = (const float*)d_in[16];
    const float* W1    = (const float*)d_in[17];
    const float* b1    = (const float*)d_in[18];
    const float* W2    = (const float*)d_in[19];
    const float* b2    = (const float*)d_in[20];
    float* out = (float*)d_out;

    conv_kernel<<<12500, 256>>>((const float4*)nodes);
    query_kernel<<<(NP + 127) / 128, 128>>>(parts, grep, q_W, q_b, key_W, key_b);
    count_kernel<<<(NE + 255) / 256, 256>>>(dst);
    scan_kernel<<<1, 1024>>>();
    scatter_kernel<<<(NE + 255) / 256, 256>>>(src, dst);

    // constant folds + gh (independent of the aggregation chain)
    sgemm_kernel<0><<<dim3(1, 3), 256>>>(val_W, W_ih, nullptr, 128);
    vb2_kernel<<<1, 384>>>(W_ih, val_b);
    sgemm_kernel<1><<<dim3((NP + 127) / 128, 3), 256>>>(parts, W_hh, b_hh, NP);

    aggregate_kernel<<<(NP + 3) / 4, 128>>>();
    sgemm_kernel<2><<<dim3((NP + 127) / 128, 3), 256>>>(nullptr, nullptr, b_ih, NP);

    gru_kernel<<<(NP + 15) / 16, 128>>>(parts, ln_g, ln_b, W1, b1, W2, b2, out);
}